// round 10
// baseline (speedup 1.0000x reference)
#include <cuda_runtime.h>
#include <cuda_fp16.h>
#include <math.h>

// ---------------- problem constants ----------------
#define NB    8      // batch
#define BCAP  32     // B_ input capsules
#define NC    32     // C_ output capsules
#define WIN   14
#define WOUT  6
#define WW    36     // WOUT*WOUT
#define BKK   288    // K*K*B_
#define CWW   1152   // C_*WOUT*WOUT
#define EPSV  1e-10f
#define HALF_LN2PI 0.91893853320467274178f
#define LOG2E 1.4426950408889634074f
#define FULLM 0xffffffffu

// ---------------- device scratch (static: allocation-free) ----------------
__device__ __half g_votes_h[(size_t)NB * CWW * BKK * 16];  // 81 MB fp16 votes [b][x][i][h]
__device__ float  g_ap[(size_t)NB * CWW * BKK];            // R numerators [b][x][i]
__device__ float  g_part[NB * 36 * BKK];                   // stage-1 partial sums
__device__ float  g_denom[NB * BKK];                       // denom[b][i]

__device__ __forceinline__ float4 rowmul(float4 wr, float4 p0, float4 p1, float4 p2, float4 p3) {
    float4 r;
    r.x = wr.x*p0.x + wr.y*p1.x + wr.z*p2.x + wr.w*p3.x;
    r.y = wr.x*p0.y + wr.y*p1.y + wr.z*p2.y + wr.w*p3.y;
    r.z = wr.x*p0.z + wr.y*p1.z + wr.z*p2.z + wr.w*p3.z;
    r.w = wr.x*p0.w + wr.y*p1.w + wr.z*p2.w + wr.w*p3.w;
    return r;
}

__device__ __forceinline__ unsigned int h2u(__half2 x) {
    return *reinterpret_cast<unsigned int*>(&x);
}

__device__ __forceinline__ float ex2f(float x) {
    float y;
    asm("ex2.approx.ftz.f32 %0, %1;" : "=f"(y) : "f"(x));
    return y;
}

__device__ __forceinline__ float rcpf(float x) {
    float y;
    asm("rcp.approx.ftz.f32 %0, %1;" : "=f"(y) : "f"(x));
    return y;
}

// TWO output columns per block: x0 = s*32 + 2j, x1 = x0+1 (same spatial s, adjacent c).
// 288 threads = 36 g x 8 q; thread (g,q) owns V[i=g+36k, h=2q..2q+1], k=0..7, both columns.
// Rw packed float2 (col0,col1) -> one LDS.64 per k serves both columns.
// Parallel tails: warp-0 lanes 0-15 finalize col0, lanes 16-31 finalize col1.
// PHASE 0: compute+store fp16 votes (pose patch shared, W rows contiguous). 1: mid. 2: out.
template <int PHASE>
__global__ __launch_bounds__(BKK, 4)
void em_kernel(const float* __restrict__ poses, const float* __restrict__ act,
               const float* __restrict__ Wt, const float* __restrict__ beta_v,
               const float* __restrict__ beta_a, const float* __restrict__ lam,
               float* __restrict__ out)
{
    const int m   = blockIdx.x;       // 0..575
    const int b   = blockIdx.y;
    const int c0  = (m & 15) * 2;     // columns c0, c0+1
    const int s   = m >> 4;
    const int yw  = s / WOUT;
    const int xw  = s - yw * WOUT;
    const int t   = threadIdx.x;
    const int g   = t >> 3;           // 0..35
    const int q   = t & 7;            // 0..7 (h-pair)
    const int w   = t >> 5;           // warp 0..8
    const int lane = t & 31;
    const size_t colbase0 = (size_t)(b * CWW + s * 32 + c0) * BKK;
    const size_t colbase1 = colbase0 + BKK;

    __shared__ float2 Rw[BKK];                 // (col0, col1)
    __shared__ float2 redm[2][9][8];           // Rw*V partials per column
    __shared__ float2 redv[2][9][8];           // Rw*V^2 partials per column
    __shared__ float  red2[2][9];              // Rw partials per column
    __shared__ float  mu_s[2][16], il2_s[2][16], nlc2_s[2][16];
    __shared__ float  a_s[2];

    // ---- per-capsule data (thread t <-> capsule i = t) ----
    const int i  = t;
    const int Bc = i / 9, uv = i - Bc * 9, u = uv / 3, v = uv - u * 3;
    const float av = act[((b * BCAP + Bc) * WIN + (2 * xw + u)) * WIN + (2 * yw + v)];

    __half2 vh0[8], vh1[8];
    const __half2* vp0 = reinterpret_cast<const __half2*>(g_votes_h + colbase0 * 16) + q;
    const __half2* vp1 = reinterpret_cast<const __half2*>(g_votes_h + colbase1 * 16) + q;

    if (PHASE == 0) {
        const float4* Pp = reinterpret_cast<const float4*>(
            poses + ((size_t)((b * BCAP + Bc) * WIN + (2 * xw + u)) * WIN + (2 * yw + v)) * 16);
        float4 p0 = Pp[0], p1 = Pp[1], p2 = Pp[2], p3 = Pp[3];
        const float4* Wp = reinterpret_cast<const float4*>(
            Wt + (size_t)(((Bc * 3 + u) * 3 + v) * NC + c0) * 16);
        #pragma unroll
        for (int col = 0; col < 2; col++) {
            float4 w0 = Wp[4*col+0], w1 = Wp[4*col+1], w2 = Wp[4*col+2], w3 = Wp[4*col+3];
            float4 r0 = rowmul(w0, p0, p1, p2, p3);
            float4 r1 = rowmul(w1, p0, p1, p2, p3);
            float4 r2 = rowmul(w2, p0, p1, p2, p3);
            float4 r3 = rowmul(w3, p0, p1, p2, p3);
            uint4 u0 = make_uint4(h2u(__floats2half2_rn(r0.x, r0.y)), h2u(__floats2half2_rn(r0.z, r0.w)),
                                  h2u(__floats2half2_rn(r1.x, r1.y)), h2u(__floats2half2_rn(r1.z, r1.w)));
            uint4 u1 = make_uint4(h2u(__floats2half2_rn(r2.x, r2.y)), h2u(__floats2half2_rn(r2.z, r2.w)),
                                  h2u(__floats2half2_rn(r3.x, r3.y)), h2u(__floats2half2_rn(r3.z, r3.w)));
            uint4* vg = reinterpret_cast<uint4*>(
                g_votes_h + (col ? colbase1 : colbase0) * 16 + (size_t)i * 16);
            vg[0] = u0; vg[1] = u1;
        }
        Rw[i] = make_float2((1.0f / 32.0f) * av, (1.0f / 32.0f) * av);
        __syncthreads();   // votes visible block-wide; Rw visible
        #pragma unroll
        for (int k = 0; k < 8; k++) {
            vh0[k] = vp0[(g + 36 * k) * 8];
            vh1[k] = vp1[(g + 36 * k) * 8];
        }
    } else {
        // prefetch votes FIRST so DRAM latency overlaps Rw fill + barrier
        #pragma unroll
        for (int k = 0; k < 8; k++) {
            vh0[k] = vp0[(g + 36 * k) * 8];
            vh1[k] = vp1[(g + 36 * k) * 8];
        }
        const float rdn = rcpf(g_denom[b * BKK + i] + EPSV);   // denom shared by columns
        const float R0  = g_ap[colbase0 + i] * rdn + EPSV;
        const float R1  = g_ap[colbase1 + i] * rdn + EPSV;
        Rw[i] = make_float2(R0 * av, R1 * av);
        __syncthreads();
    }

    // ---- fused statistics pass (both columns) ----
    float2 am0 = make_float2(0.f,0.f), av0 = make_float2(0.f,0.f);
    float2 am1 = make_float2(0.f,0.f), av1 = make_float2(0.f,0.f);
    float  ar0 = 0.f, ar1 = 0.f;
    #pragma unroll
    for (int k = 0; k < 8; k++) {
        const float2 rw = Rw[g + 36 * k];
        const float2 v0 = __half22float2(vh0[k]);
        const float2 v1 = __half22float2(vh1[k]);
        float tx = rw.x * v0.x, ty = rw.x * v0.y;
        am0.x += tx; am0.y += ty;
        av0.x = fmaf(tx, v0.x, av0.x); av0.y = fmaf(ty, v0.y, av0.y);
        ar0 += rw.x;
        tx = rw.y * v1.x; ty = rw.y * v1.y;
        am1.x += tx; am1.y += ty;
        av1.x = fmaf(tx, v1.x, av1.x); av1.y = fmaf(ty, v1.y, av1.y);
        ar1 += rw.y;
    }
    #pragma unroll
    for (int d = 8; d <= 16; d <<= 1) {
        am0.x += __shfl_xor_sync(FULLM, am0.x, d);
        am0.y += __shfl_xor_sync(FULLM, am0.y, d);
        av0.x += __shfl_xor_sync(FULLM, av0.x, d);
        av0.y += __shfl_xor_sync(FULLM, av0.y, d);
        ar0   += __shfl_xor_sync(FULLM, ar0,   d);
        am1.x += __shfl_xor_sync(FULLM, am1.x, d);
        am1.y += __shfl_xor_sync(FULLM, am1.y, d);
        av1.x += __shfl_xor_sync(FULLM, av1.x, d);
        av1.y += __shfl_xor_sync(FULLM, av1.y, d);
        ar1   += __shfl_xor_sync(FULLM, ar1,   d);
    }
    // lanes 0-7 store col0 partials, lanes 8-15 store col1 (values replicated by xor-reduce)
    if (lane < 8)            { redm[0][w][lane]   = am0; redv[0][w][lane]   = av0; }
    else if (lane < 16)      { redm[1][w][lane-8] = am1; redv[1][w][lane-8] = av1; }
    else if (lane == 16)     red2[0][w] = ar0;
    else if (lane == 17)     red2[1][w] = ar1;
    __syncthreads();

    // ---- parallel tails: warp 0, lanes 0-15 -> col0, lanes 16-31 -> col1 ----
    if (t < 32) {
        const int col = t >> 4, hh = t & 15;
        const float* rm = reinterpret_cast<const float*>(redm[col]);
        const float* rv = reinterpret_cast<const float*>(redv[col]);
        float rsum = 0.f, vsum = 0.f, sr = 0.f;
        #pragma unroll
        for (int j = 0; j < 9; j++) {
            rsum += rm[j * 16 + hh];
            vsum += rv[j * 16 + hh];
            sr   += red2[col][j];
        }
        const float rs = rcpf(sr);
        const float mu = rsum * rs;
        const float sig = fmaxf(vsum * rs - mu * mu, 1e-12f);
        const float ls = 0.5f * __logf(sig);        // log(sqrt(sig))
        if (PHASE == 2) {
            out[(size_t)(b * CWW + (c0 + col) * WW + s) * 16 + hh] = mu;
        } else {
            mu_s[col][hh]   = mu;
            il2_s[col][hh]  = (0.5f * LOG2E) * rcpf(sig);
            nlc2_s[col][hh] = -(ls + HALF_LN2PI) * LOG2E;
        }
        float lsum = ls;
        lsum += __shfl_xor_sync(FULLM, lsum, 1);
        lsum += __shfl_xor_sync(FULLM, lsum, 2);
        lsum += __shfl_xor_sync(FULLM, lsum, 4);
        lsum += __shfl_xor_sync(FULLM, lsum, 8);
        if (hh == 0) {
            const float cost = sr * (16.f * beta_v[c0 + col] + lsum);
            const float z = lam[0] * (beta_a[c0 + col] - cost);
            const float aa = 1.f / (1.f + __expf(-z));
            if (PHASE == 2) out[(size_t)NB * CWW * 16 + b * CWW + (c0 + col) * WW + s] = aa;
            else            a_s[col] = aa;
        }
    }
    if (PHASE == 2) return;
    __syncthreads();

    // ---- p-pass, both columns: ap[i] = a * sum_h exp2(-d^2*il2 + nlc2) ----
    const float  an0 = a_s[0], an1 = a_s[1];
    const float2 mu20 = make_float2(mu_s[0][2*q], mu_s[0][2*q+1]);
    const float2 il0  = make_float2(il2_s[0][2*q], il2_s[0][2*q+1]);
    const float2 lc0  = make_float2(nlc2_s[0][2*q], nlc2_s[0][2*q+1]);
    const float2 mu21 = make_float2(mu_s[1][2*q], mu_s[1][2*q+1]);
    const float2 il1  = make_float2(il2_s[1][2*q], il2_s[1][2*q+1]);
    const float2 lc1  = make_float2(nlc2_s[1][2*q], nlc2_s[1][2*q+1]);
    #pragma unroll
    for (int k = 0; k < 8; k++) {
        const float2 v0 = __half22float2(vh0[k]);
        const float2 v1 = __half22float2(vh1[k]);
        const float dx0 = v0.x - mu20.x, dy0 = v0.y - mu20.y;
        const float dx1 = v1.x - mu21.x, dy1 = v1.y - mu21.y;
        float p0 = ex2f(fmaf(-dx0*dx0, il0.x, lc0.x)) + ex2f(fmaf(-dy0*dy0, il0.y, lc0.y));
        float p1 = ex2f(fmaf(-dx1*dx1, il1.x, lc1.x)) + ex2f(fmaf(-dy1*dy1, il1.y, lc1.y));
        p0 += __shfl_xor_sync(FULLM, p0, 1);
        p1 += __shfl_xor_sync(FULLM, p1, 1);
        p0 += __shfl_xor_sync(FULLM, p0, 2);
        p1 += __shfl_xor_sync(FULLM, p1, 2);
        p0 += __shfl_xor_sync(FULLM, p0, 4);
        p1 += __shfl_xor_sync(FULLM, p1, 4);
        if (q == 0) {   // lanes g=4w..4w+3: one 16B segment per column
            g_ap[colbase0 + g + 36 * k] = an0 * p0;
            g_ap[colbase1 + g + 36 * k] = an1 * p1;
        }
    }
}

// Stage 1: block (j,b) sums 32 consecutive x-rows of ap -> g_part[b][j][i].
__global__ __launch_bounds__(BKK)
void denom_part_kernel()
{
    const int j = blockIdx.x;       // 0..35
    const int b = blockIdx.y;
    const int i = threadIdx.x;
    const float* ap = g_ap + (size_t)(b * CWW + j * 32) * BKK + i;
    float sv = 0.f;
    #pragma unroll 8
    for (int r = 0; r < 32; r++) sv += ap[(size_t)r * BKK];
    g_part[(b * 36 + j) * BKK + i] = sv;
}

// Stage 2: denom[b][i] = sum of the 36 partials.
__global__ __launch_bounds__(BKK)
void denom_final_kernel()
{
    const int b = blockIdx.x;
    const int i = threadIdx.x;
    const float* pp = g_part + b * 36 * BKK + i;
    float sv = 0.f;
    #pragma unroll
    for (int j = 0; j < 36; j++) sv += pp[j * BKK];
    g_denom[b * BKK + i] = sv;
}

extern "C" void kernel_launch(void* const* d_in, const int* in_sizes, int n_in,
                              void* d_out, int out_size)
{
    (void)in_sizes; (void)n_in; (void)out_size;
    const float* poses = (const float*)d_in[0];
    const float* act   = (const float*)d_in[1];
    const float* Wt    = (const float*)d_in[2];
    const float* bv    = (const float*)d_in[3];
    const float* ba    = (const float*)d_in[4];
    const float* lam   = (const float*)d_in[5];
    float* out = (float*)d_out;

    dim3 grid(CWW / 2, NB);
    em_kernel<0><<<grid, BKK>>>(poses, act, Wt, bv, ba, lam, out);
    denom_part_kernel<<<dim3(36, NB), BKK>>>();
    denom_final_kernel<<<NB, BKK>>>();
    em_kernel<1><<<grid, BKK>>>(poses, act, Wt, bv, ba, lam, out);
    denom_part_kernel<<<dim3(36, NB), BKK>>>();
    denom_final_kernel<<<NB, BKK>>>();
    em_kernel<2><<<grid, BKK>>>(poses, act, Wt, bv, ba, lam, out);
}

// round 11
// speedup vs baseline: 1.4289x; 1.4289x over previous
#include <cuda_runtime.h>
#include <cuda_fp16.h>
#include <math.h>

// ---------------- problem constants ----------------
#define NB    8      // batch
#define BCAP  32     // B_ input capsules
#define NC    32     // C_ output capsules
#define WIN   14
#define WOUT  6
#define WW    36     // WOUT*WOUT
#define BKK   288    // K*K*B_
#define CWW   1152   // C_*WOUT*WOUT
#define EPSV  1e-10f
#define HALF_LN2PI 0.91893853320467274178f
#define LOG2E 1.4426950408889634074f
#define FULLM 0xffffffffu

// ---------------- device scratch (static: allocation-free) ----------------
__device__ __half g_votes_h[(size_t)NB * CWW * BKK * 16];  // 81 MB fp16 votes [b][x][i][h]
__device__ float  g_ap[(size_t)NB * CWW * BKK];            // R numerators [b][x][i]
__device__ float  g_part[NB * 36 * BKK];                   // stage-1 partial sums
__device__ float  g_denom[NB * BKK];                       // denom[b][i]

__device__ __forceinline__ float4 rowmul(float4 wr, float4 p0, float4 p1, float4 p2, float4 p3) {
    float4 r;
    r.x = wr.x*p0.x + wr.y*p1.x + wr.z*p2.x + wr.w*p3.x;
    r.y = wr.x*p0.y + wr.y*p1.y + wr.z*p2.y + wr.w*p3.y;
    r.z = wr.x*p0.z + wr.y*p1.z + wr.z*p2.z + wr.w*p3.z;
    r.w = wr.x*p0.w + wr.y*p1.w + wr.z*p2.w + wr.w*p3.w;
    return r;
}

__device__ __forceinline__ unsigned int h2u(__half2 x) {
    return *reinterpret_cast<unsigned int*>(&x);
}

__device__ __forceinline__ float ex2f(float x) {
    float y;
    asm("ex2.approx.ftz.f32 %0, %1;" : "=f"(y) : "f"(x));
    return y;
}

__device__ __forceinline__ float rcpf(float x) {
    float y;
    asm("rcp.approx.ftz.f32 %0, %1;" : "=f"(y) : "f"(x));
    return y;
}

// One block per output column. blockIdx.x = x = s*32 + c. 288 threads = 36 g x 8 q.
// Stats pass: thread (g,q) owns V[i=g+36k, h=2q..2q+1], k=0..7 (coalesced half2
// column loads, prefetched before the Rw fill so DRAM latency overlaps).
// p-pass: thread t re-reads its OWN row V[i=t][0..15] (32 contiguous bytes,
// L1/L2-hot) and sums over h serially in registers — no shuffles, no staging,
// and the g_ap store is one fully-coalesced 1152B line per block.
// Tail packs per-h constants into cst[8][8]: [hp] = {mu.x,mu.y,il.x,il.y,lc.x,lc.y,-,-}.
// PHASE 0: compute+store fp16 votes (row kept in regs). 1: mid iter. 2: outputs.
template <int PHASE>
__global__ __launch_bounds__(BKK, 5)
void em_kernel(const float* __restrict__ poses, const float* __restrict__ act,
               const float* __restrict__ Wt, const float* __restrict__ beta_v,
               const float* __restrict__ beta_a, const float* __restrict__ lam,
               float* __restrict__ out)
{
    const int x   = blockIdx.x;
    const int b   = blockIdx.y;
    const int c   = x & 31;
    const int s   = x >> 5;
    const int yw  = s / WOUT;
    const int xw  = s - yw * WOUT;
    const int t   = threadIdx.x;
    const int g   = t >> 3;        // 0..35
    const int q   = t & 7;         // 0..7 (h-pair)
    const int w   = t >> 5;        // warp 0..8
    const int lane = t & 31;
    const size_t colbase = (size_t)(b * CWW + x) * BKK;

    __shared__ float  Rw[BKK];
    __shared__ float2 redm[9][8];        // Rw*V partials (float[9][16] view)
    __shared__ float2 redv[9][8];        // Rw*V^2 partials
    __shared__ float  red2[9];           // Rw partials
    __shared__ float  cst[8][8];         // per-h-pair constants for the p-pass
    __shared__ float  a_s;

    // ---- Rw fill (thread t <-> capsule i = t) ----
    const int i  = t;
    const int Bc = i / 9, uv = i - Bc * 9, u = uv / 3, v = uv - u * 3;
    const float av = act[((b * BCAP + Bc) * WIN + (2 * xw + u)) * WIN + (2 * yw + v)];

    float2 Vr[8];
    uint4 row0, row1;   // this thread's own vote row V[i][0..15] as 8x half2
    const __half2* vp = reinterpret_cast<const __half2*>(g_votes_h + colbase * 16) + q;

    if (PHASE == 0) {
        const float4* Pp = reinterpret_cast<const float4*>(
            poses + ((size_t)((b * BCAP + Bc) * WIN + (2 * xw + u)) * WIN + (2 * yw + v)) * 16);
        const float4* Wp = reinterpret_cast<const float4*>(
            Wt + (size_t)(((Bc * 3 + u) * 3 + v) * NC + c) * 16);
        float4 p0 = Pp[0], p1 = Pp[1], p2 = Pp[2], p3 = Pp[3];
        float4 w0 = Wp[0], w1 = Wp[1], w2 = Wp[2], w3 = Wp[3];
        float4 r0 = rowmul(w0, p0, p1, p2, p3);
        float4 r1 = rowmul(w1, p0, p1, p2, p3);
        float4 r2 = rowmul(w2, p0, p1, p2, p3);
        float4 r3 = rowmul(w3, p0, p1, p2, p3);
        row0 = make_uint4(h2u(__floats2half2_rn(r0.x, r0.y)), h2u(__floats2half2_rn(r0.z, r0.w)),
                          h2u(__floats2half2_rn(r1.x, r1.y)), h2u(__floats2half2_rn(r1.z, r1.w)));
        row1 = make_uint4(h2u(__floats2half2_rn(r2.x, r2.y)), h2u(__floats2half2_rn(r2.z, r2.w)),
                          h2u(__floats2half2_rn(r3.x, r3.y)), h2u(__floats2half2_rn(r3.z, r3.w)));
        uint4* vg = reinterpret_cast<uint4*>(g_votes_h + colbase * 16 + (size_t)i * 16);
        vg[0] = row0; vg[1] = row1;
        Rw[i] = (1.0f / 32.0f) * av;
        __syncthreads();   // votes visible block-wide; Rw visible
        #pragma unroll
        for (int k = 0; k < 8; k++) Vr[k] = __half22float2(vp[(g + 36 * k) * 8]);
    } else {
        // prefetch column slices FIRST so DRAM latency overlaps Rw fill + barrier
        __half2 vh[8];
        #pragma unroll
        for (int k = 0; k < 8; k++) vh[k] = vp[(g + 36 * k) * 8];
        const float R = g_ap[colbase + i] * rcpf(g_denom[b * BKK + i] + EPSV) + EPSV;
        Rw[i] = R * av;
        __syncthreads();
        #pragma unroll
        for (int k = 0; k < 8; k++) Vr[k] = __half22float2(vh[k]);
    }

    // ---- fused statistics pass: sum Rw*V, Rw*V^2, Rw ----
    float2 accm = make_float2(0.f, 0.f);
    float2 accv = make_float2(0.f, 0.f);
    float  accr = 0.f;
    #pragma unroll
    for (int k = 0; k < 8; k++) {
        const float rw = Rw[g + 36 * k];
        const float tx = rw * Vr[k].x;
        const float ty = rw * Vr[k].y;
        accm.x += tx;                 accm.y += ty;
        accv.x = fmaf(tx, Vr[k].x, accv.x);
        accv.y = fmaf(ty, Vr[k].y, accv.y);
        accr += rw;
    }
    accm.x += __shfl_xor_sync(FULLM, accm.x, 8);
    accm.y += __shfl_xor_sync(FULLM, accm.y, 8);
    accv.x += __shfl_xor_sync(FULLM, accv.x, 8);
    accv.y += __shfl_xor_sync(FULLM, accv.y, 8);
    accr   += __shfl_xor_sync(FULLM, accr,   8);
    accm.x += __shfl_xor_sync(FULLM, accm.x, 16);
    accm.y += __shfl_xor_sync(FULLM, accm.y, 16);
    accv.x += __shfl_xor_sync(FULLM, accv.x, 16);
    accv.y += __shfl_xor_sync(FULLM, accv.y, 16);
    accr   += __shfl_xor_sync(FULLM, accr,   16);
    if (lane < 8) {
        redm[w][lane] = accm;
        redv[w][lane] = accv;
        if (lane == 0) red2[w] = accr;
    }
    __syncthreads();

    // ---- issue the row re-load NOW (phases 0/1) so it overlaps the serial tail ----
    if (PHASE != 2 && PHASE != 0) {
        const uint4* vg = reinterpret_cast<const uint4*>(g_votes_h + colbase * 16 + (size_t)i * 16);
        row0 = vg[0]; row1 = vg[1];   // L1/L2 hot: same 9KB the block just read as columns
    }

    // ---- serial tail: 16 threads compute per-h stats ----
    if (t < 16) {
        const float* rm = reinterpret_cast<const float*>(redm);
        const float* rv = reinterpret_cast<const float*>(redv);
        float rsum = 0.f, vsum = 0.f, sr = 0.f;
        #pragma unroll
        for (int j = 0; j < 9; j++) {
            rsum += rm[j * 16 + t];
            vsum += rv[j * 16 + t];
            sr   += red2[j];
        }
        const float rs = rcpf(sr);
        const float mu = rsum * rs;
        const float sig = fmaxf(vsum * rs - mu * mu, 1e-12f);
        const float ls = 0.5f * __logf(sig);          // log(sqrt(sig))
        if (PHASE == 2) {
            out[(size_t)(b * CWW + c * WW + s) * 16 + t] = mu;
        } else {
            const int hp = t >> 1, par = t & 1;
            cst[hp][par]     = mu;
            cst[hp][2 + par] = (0.5f * LOG2E) * rcpf(sig);
            cst[hp][4 + par] = -(ls + HALF_LN2PI) * LOG2E;
        }
        float lsum = ls;
        lsum += __shfl_xor_sync(0x0000ffffu, lsum, 1);
        lsum += __shfl_xor_sync(0x0000ffffu, lsum, 2);
        lsum += __shfl_xor_sync(0x0000ffffu, lsum, 4);
        lsum += __shfl_xor_sync(0x0000ffffu, lsum, 8);
        if (t == 0) {
            const float cost = sr * (16.f * beta_v[c] + lsum);
            const float z = lam[0] * (beta_a[c] - cost);
            const float aa = 1.f / (1.f + __expf(-z));
            if (PHASE == 2) out[(size_t)NB * CWW * 16 + b * CWW + c * WW + s] = aa;
            else            a_s = aa;
        }
    }
    if (PHASE == 2) return;
    __syncthreads();

    // ---- p-pass (row-major): thread t sums over all 16 h of its own row i=t ----
    const __half2 rowh[8] = {
        *reinterpret_cast<const __half2*>(&row0.x), *reinterpret_cast<const __half2*>(&row0.y),
        *reinterpret_cast<const __half2*>(&row0.z), *reinterpret_cast<const __half2*>(&row0.w),
        *reinterpret_cast<const __half2*>(&row1.x), *reinterpret_cast<const __half2*>(&row1.y),
        *reinterpret_cast<const __half2*>(&row1.z), *reinterpret_cast<const __half2*>(&row1.w)
    };
    float ap_acc = 0.f;
    #pragma unroll
    for (int hp = 0; hp < 8; hp++) {
        const float4 c0 = *reinterpret_cast<const float4*>(&cst[hp][0]);  // mu.x mu.y il.x il.y
        const float2 c1 = *reinterpret_cast<const float2*>(&cst[hp][4]);  // lc.x lc.y
        const float2 vv = __half22float2(rowh[hp]);
        const float dx = vv.x - c0.x;
        const float dy = vv.y - c0.y;
        ap_acc += ex2f(fmaf(-dx * dx, c0.z, c1.x)) + ex2f(fmaf(-dy * dy, c0.w, c1.y));
    }
    g_ap[colbase + t] = a_s * ap_acc;   // one fully-coalesced 1152B store per block
}

// Stage 1: block (j,b) sums 32 consecutive x-rows of ap -> g_part[b][j][i].
__global__ __launch_bounds__(BKK)
void denom_part_kernel()
{
    const int j = blockIdx.x;       // 0..35
    const int b = blockIdx.y;
    const int i = threadIdx.x;
    const float* ap = g_ap + (size_t)(b * CWW + j * 32) * BKK + i;
    float sv = 0.f;
    #pragma unroll 8
    for (int r = 0; r < 32; r++) sv += ap[(size_t)r * BKK];
    g_part[(b * 36 + j) * BKK + i] = sv;
}

// Stage 2: denom[b][i] = sum of the 36 partials.
__global__ __launch_bounds__(BKK)
void denom_final_kernel()
{
    const int b = blockIdx.x;
    const int i = threadIdx.x;
    const float* pp = g_part + b * 36 * BKK + i;
    float sv = 0.f;
    #pragma unroll
    for (int j = 0; j < 36; j++) sv += pp[j * BKK];
    g_denom[b * BKK + i] = sv;
}

extern "C" void kernel_launch(void* const* d_in, const int* in_sizes, int n_in,
                              void* d_out, int out_size)
{
    (void)in_sizes; (void)n_in; (void)out_size;
    const float* poses = (const float*)d_in[0];
    const float* act   = (const float*)d_in[1];
    const float* Wt    = (const float*)d_in[2];
    const float* bv    = (const float*)d_in[3];
    const float* ba    = (const float*)d_in[4];
    const float* lam   = (const float*)d_in[5];
    float* out = (float*)d_out;

    dim3 grid(CWW, NB);
    em_kernel<0><<<grid, BKK>>>(poses, act, Wt, bv, ba, lam, out);
    denom_part_kernel<<<dim3(36, NB), BKK>>>();
    denom_final_kernel<<<NB, BKK>>>();
    em_kernel<1><<<grid, BKK>>>(poses, act, Wt, bv, ba, lam, out);
    denom_part_kernel<<<dim3(36, NB), BKK>>>();
    denom_final_kernel<<<NB, BKK>>>();
    em_kernel<2><<<grid, BKK>>>(poses, act, Wt, bv, ba, lam, out);
}